// round 13
// baseline (speedup 1.0000x reference)
#include <cuda_runtime.h>

#define NAGENTS 8192
#define OBSLEN  20
#define PREDLEN 30
#define EMBED   64
#define HIDDEN  128
#define CNNOUT  2048
#define GATES   512   /* 4*HIDDEN */
#define KDIM    192   /* EMBED + HIDDEN */

// Weight layout (unit-paired, COALESCED): ulonglong2 view [k][h][s][lane],
//   s in {0,1}: s=0 -> ( (Wlo,Whi)@e0 , (Wlo,Whi)@e1 ), s=1 -> e2,e3.
//   j_lo = e*128 + h*64 + lane, j_hi = j_lo + 32  (units lane, lane+32 of half h).
// LDG.128 at fixed (k,h,s): lane stride 16B -> contiguous 512B = 4 wavefronts.
// Per-k stride = 128 ulonglong2. Extra zero k-row pads the prefetch.
__device__ unsigned long long g_Wd[(KDIM + 1) * 2 * 2 * 32 * 2];
__device__ float g_bias[GATES];
__device__ float g_imgproj[NAGENTS * 2];

// ---------------------------------------------------------------------------
// Combined prep: blocks [0,1024) img projection; [1024,1408) weights+bias.
// ---------------------------------------------------------------------------
__global__ void prep_all(const float* __restrict__ img,
                         const float* __restrict__ pred_W,
                         const float* __restrict__ W_ih,
                         const float* __restrict__ W_hh,
                         const float* __restrict__ b_ih,
                         const float* __restrict__ b_hh) {
    int bid = blockIdx.x;
    if (bid < 1024) {
        int warp = threadIdx.x >> 5, lane = threadIdx.x & 31;
        int n = bid * 8 + warp;
        const float4* ip = (const float4*)(img + (size_t)n * CNNOUT);
        const float4* w0 = (const float4*)(pred_W + HIDDEN);
        const float4* w1 = (const float4*)(pred_W + (HIDDEN + CNNOUT) + HIDDEN);
        float s0 = 0.f, s1 = 0.f;
        for (int i = lane; i < CNNOUT / 4; i += 32) {
            float4 v = ip[i], a = w0[i], b = w1[i];
            s0 += v.x * a.x + v.y * a.y + v.z * a.z + v.w * a.w;
            s1 += v.x * b.x + v.y * b.y + v.z * b.z + v.w * b.w;
        }
#pragma unroll
        for (int o = 16; o; o >>= 1) {
            s0 += __shfl_xor_sync(0xFFFFFFFFu, s0, o);
            s1 += __shfl_xor_sync(0xFFFFFFFFu, s1, o);
        }
        if (lane == 0) { g_imgproj[n * 2] = s0; g_imgproj[n * 2 + 1] = s1; }
    } else {
        int idx = (bid - 1024) * 256 + threadIdx.x;
        if (idx < KDIM * GATES) {
            int k = idx / GATES, j = idx % GATES;
            int e = j >> 7, r = j & 127;
            int h = r >> 6, l6 = r & 63;
            int lane = l6 & 31, hi = l6 >> 5;     // hi: 0 = j_lo, 1 = j_hi
            int s = e >> 1;
            float v = (k < EMBED) ? W_ih[j * EMBED + k] : W_hh[j * HIDDEN + (k - EMBED)];
            ((float*)g_Wd)[(((((k * 2 + h) * 2 + s) * 32 + lane)) << 2) + (e & 1) * 2 + hi] = v;
        }
        if (idx < GATES) g_bias[idx] = b_ih[idx] + b_hh[idx];
    }
}

__device__ __forceinline__ float sigf(float x) {
    return __fdividef(1.f, 1.f + __expf(-x));
}
__device__ __forceinline__ float tanhfast(float x) {
    float e = __expf(-2.f * fabsf(x));
    float r = __fdividef(1.f - e, 1.f + e);
    return copysignf(r, x);
}

__device__ __forceinline__ unsigned long long pack2(float lo, float hi) {
    unsigned long long r;
    asm("mov.b64 %0, {%1, %2};" : "=l"(r) : "f"(lo), "f"(hi));
    return r;
}
__device__ __forceinline__ float2 unpk(unsigned long long v) {
    float2 r;
    asm("mov.b64 {%0, %1}, %2;" : "=f"(r.x), "=f"(r.y) : "l"(v));
    return r;
}
#define FF2(a, w, i) asm("fma.rn.f32x2 %0, %1, %2, %0;" : "+l"(a) : "l"(w), "l"(i))
#define BARW(id) asm volatile("bar.sync %0, 64;" :: "r"(id) : "memory")

#define ROWPAD 10   /* ull per in_dup row (8 data + 2 pad; spreads STS banks) */
#define IN_DUP_ULL (4 * KDIM * ROWPAD)
#define CS_FLOATS (4 * 4 * 32 * 8)
#define SMEM_BYTES (IN_DUP_ULL * 8 + 256 * 8 + (CS_FLOATS + 192 + 256 + 192 + 32) * 4)

// ---------------------------------------------------------------------------
// 256 threads = 4 warp-pairs; 8 agents per pair. Warp (2g+half) owns units
// half*64+lane (m=0) and half*64+32+lane (m=1). f32x2 pairs UNITS; weights
// arrive prepacked+coalesced from gmem (ZERO pack MOVs in the GEMM loop);
// inputs pre-duplicated (v,v) in smem; c state in smem (reg relief: keeps
// ptxas below the 128-reg cap where fma.rn.f32x2 gets demoted to 2x FFMA).
// ---------------------------------------------------------------------------
__global__ __launch_bounds__(256, 2) void lstm_main(
    const float* __restrict__ obs_pos, const int* __restrict__ hist,
    const float* __restrict__ obs_rel, const float* __restrict__ h0,
    const float* __restrict__ embed_W, const float* __restrict__ embed_b,
    const float* __restrict__ pred_W,  const float* __restrict__ pred_b,
    float* __restrict__ out) {
    extern __shared__ unsigned long long smu[];
    unsigned long long (*in_dup)[KDIM][ROWPAD] =
        (unsigned long long(*)[KDIM][ROWPAD])smu;                 // [g][k][a]=(v,v)
    unsigned long long (*b2_s)[32][4] =
        (unsigned long long(*)[32][4])(smu + IN_DUP_ULL);         // [h][lane][e]
    float* fb = (float*)(smu + IN_DUP_ULL + 256);
    float (*c_s)[4][32][8] = (float(*)[4][32][8])fb;              // [g][hm][lane][a]
    float* ew0 = fb + CS_FLOATS;  // 64
    float* ew1 = ew0 + 64;
    float* eb  = ew1 + 64;
    float* pw  = eb + 64;         // [2][128]
    float (*src_s)[8][2]  = (float(*)[8][2])(pw + 256);
    float (*pos_s)[8][2]  = (float(*)[8][2])(pw + 256 + 64);
    float (*imgp_s)[8][2] = (float(*)[8][2])(pw + 256 + 128);
    int*   hist_s         = (int*)(pw + 256 + 192);

    int tid = threadIdx.x, warp = tid >> 5, lane = tid & 31;
    int g = warp >> 1, half = warp & 1;
    int ab = blockIdx.x * 32;
    int a0 = g * 8;
    int barid = g + 1;

    // ---------------- init ----------------
    for (int i = tid; i < GATES; i += 256) {
        int h = i >> 7, lane_i = (i >> 2) & 31, e = i & 3;
        int jlo = e * 128 + h * 64 + lane_i;
        b2_s[h][lane_i][e] = pack2(g_bias[jlo], g_bias[jlo + 32]);
    }
    if (tid < EMBED) {
        ew0[tid] = embed_W[tid * 2];
        ew1[tid] = embed_W[tid * 2 + 1];
        eb[tid]  = embed_b[tid];
    }
    for (int i = tid; i < 2 * HIDDEN; i += 256)
        pw[i] = pred_W[(i >> 7) * (HIDDEN + CNNOUT) + (i & 127)];
    if (tid < 32) hist_s[tid] = hist[ab + tid];
    if (tid < 64) {
        int a = tid >> 1, d = tid & 1;
        pos_s[a >> 3][a & 7][d]  = obs_pos[(size_t)(ab + a) * OBSLEN * 2 + (OBSLEN - 1) * 2 + d];
        imgp_s[a >> 3][a & 7][d] = g_imgproj[(ab + a) * 2 + d];
    }
    for (int i = tid; i < IN_DUP_ULL; i += 256) {
        int k = (i / ROWPAD) % KDIM;
        float v = (k < EMBED) ? 0.f : h0[k - EMBED];
        ((unsigned long long*)in_dup)[i] = pack2(v, v);
    }
#pragma unroll
    for (int m = 0; m < 2; m++) {
        float hv = h0[half * 64 + lane + 32 * m];
#pragma unroll
        for (int a = 0; a < 8; a++) c_s[g][half * 2 + m][lane][a] = hv;
    }
    float pbd = pred_b[(lane >> 2) & 1];
    __syncthreads();

    int maxh8 = hist_s[a0];
#pragma unroll
    for (int a = 1; a < 8; a++) maxh8 = max(maxh8, hist_s[a0 + a]);

    // ---------------- 49 sequential steps ----------------
    for (int step = 0; step < OBSLEN - 1 + PREDLEN; step++) {
        bool obsPhase = step < OBSLEN - 1;
        int t = obsPhase ? (step + 1) : (step - (OBSLEN - 1));

        if (obsPhase) {
            if (maxh8 <= OBSLEN - t) continue;
            if (half == 0 && lane < 16) {
                int a = lane >> 1, d = lane & 1;
                src_s[g][a][d] = obs_rel[(size_t)(ab + a0 + a) * OBSLEN * 2 + t * 2 + d];
            }
            BARW(barid);
        } else {
            // disp = h @ pred_W[:, :128].T + img_proj + pred_b
            int task = lane >> 2, sub = lane & 3;
            int a = half * 4 + (task >> 1), d = task & 1;
            const float* inf = (const float*)in_dup[g];
            float s = 0.f;
#pragma unroll 8
            for (int kk = 0; kk < 32; kk++) {
                int k = sub * 32 + kk;
                s = fmaf(pw[d * 128 + k], inf[((EMBED + k) * ROWPAD + a) * 2], s);
            }
            s += __shfl_xor_sync(0xFFFFFFFFu, s, 1);
            s += __shfl_xor_sync(0xFFFFFFFFu, s, 2);
            if (sub == 0) {
                s += imgp_s[g][a][d] + pbd;
                float p = pos_s[g][a][d] + s;
                pos_s[g][a][d] = p;
                out[(size_t)(ab + a0 + a) * PREDLEN * 2 + t * 2 + d] = p;
                src_s[g][a][d] = s;
            }
            BARW(barid);
        }

        // embed -> duplicated input rows (warp h writes rows h*32..h*32+31)
        {
            int k = half * 32 + lane;
            float w0 = ew0[k], w1 = ew1[k], bb = eb[k];
#pragma unroll
            for (int a = 0; a < 8; a++) {
                float x = fmaxf(fmaf(w0, src_s[g][a][0], fmaf(w1, src_s[g][a][1], bb)), 0.f);
                in_dup[g][k][a] = pack2(x, x);
            }
        }
        BARW(barid);

        // ---- gate GEMM: acc[e][a] = f32x2 over unit pair (lane, lane+32) ----
        // Zero pack-MOVs: weights prepacked in gmem, inputs pre-duplicated in smem.
        unsigned long long acc[4][8];
#pragma unroll
        for (int e = 0; e < 4; e++) {
            unsigned long long b = b2_s[half][lane][e];
#pragma unroll
            for (int a = 0; a < 8; a++) acc[e][a] = b;
        }
        // ull2 base: [k=0][half][s=0][lane]; s=1 at +32; per-k stride 128 ull2
        const ulonglong2* wp = (const ulonglong2*)g_Wd + (half * 2) * 32 + lane;
        const ulonglong2* inp = (const ulonglong2*)in_dup[g];
        ulonglong2 w01 = wp[0], w23 = wp[32];
#pragma unroll 2
        for (int k = 0; k < KDIM; k++) {
            const ulonglong2* np = wp + 128;     // next k (zero row pads OOB)
            ulonglong2 n01 = np[0], n23 = np[32];
            ulonglong2 iA = inp[5 * k], iB = inp[5 * k + 1];
            FF2(acc[0][0], w01.x, iA.x); FF2(acc[1][0], w01.y, iA.x);
            FF2(acc[2][0], w23.x, iA.x); FF2(acc[3][0], w23.y, iA.x);
            FF2(acc[0][1], w01.x, iA.y); FF2(acc[1][1], w01.y, iA.y);
            FF2(acc[2][1], w23.x, iA.y); FF2(acc[3][1], w23.y, iA.y);
            FF2(acc[0][2], w01.x, iB.x); FF2(acc[1][2], w01.y, iB.x);
            FF2(acc[2][2], w23.x, iB.x); FF2(acc[3][2], w23.y, iB.x);
            FF2(acc[0][3], w01.x, iB.y); FF2(acc[1][3], w01.y, iB.y);
            FF2(acc[2][3], w23.x, iB.y); FF2(acc[3][3], w23.y, iB.y);
            ulonglong2 iC = inp[5 * k + 2], iD = inp[5 * k + 3];
            FF2(acc[0][4], w01.x, iC.x); FF2(acc[1][4], w01.y, iC.x);
            FF2(acc[2][4], w23.x, iC.x); FF2(acc[3][4], w23.y, iC.x);
            FF2(acc[0][5], w01.x, iC.y); FF2(acc[1][5], w01.y, iC.y);
            FF2(acc[2][5], w23.x, iC.y); FF2(acc[3][5], w23.y, iC.y);
            FF2(acc[0][6], w01.x, iD.x); FF2(acc[1][6], w01.y, iD.x);
            FF2(acc[2][6], w23.x, iD.x); FF2(acc[3][6], w23.y, iD.x);
            FF2(acc[0][7], w01.x, iD.y); FF2(acc[1][7], w01.y, iD.y);
            FF2(acc[2][7], w23.x, iD.y); FF2(acc[3][7], w23.y, iD.y);
            w01 = n01; w23 = n23; wp = np;
        }

        // ---- cell update (c in shared); h written back duplicated ----
        bool upd[8];
#pragma unroll
        for (int a = 0; a < 8; a++)
            upd[a] = !obsPhase || (hist_s[a0 + a] > OBSLEN - t);
        float* cp0 = c_s[g][half * 2 + 0][lane];
        float* cp1 = c_s[g][half * 2 + 1][lane];
        float h2[2][8];
#pragma unroll
        for (int a = 0; a < 8; a++) {
            float2 I = unpk(acc[0][a]);
            float2 F = unpk(acc[1][a]);
            float2 G = unpk(acc[2][a]);
            float2 O = unpk(acc[3][a]);
            if (upd[a]) {
                float c20 = sigf(F.x) * cp0[a] + sigf(I.x) * tanhfast(G.x);
                float c21 = sigf(F.y) * cp1[a] + sigf(I.y) * tanhfast(G.y);
                cp0[a] = c20; cp1[a] = c21;
                h2[0][a] = sigf(O.x) * tanhfast(c20);
                h2[1][a] = sigf(O.y) * tanhfast(c21);
            } else {
                h2[0][a] = unpk(in_dup[g][EMBED + half * 64 + lane][a]).x;
                h2[1][a] = unpk(in_dup[g][EMBED + half * 64 + 32 + lane][a]).x;
            }
        }
#pragma unroll
        for (int m = 0; m < 2; m++) {
            int row = EMBED + half * 64 + 32 * m + lane;
#pragma unroll
            for (int a = 0; a < 8; a++)
                in_dup[g][row][a] = pack2(h2[m][a], h2[m][a]);
        }
        BARW(barid);   // h visible to partner warp
    }
}

extern "C" void kernel_launch(void* const* d_in, const int* in_sizes, int n_in,
                              void* d_out, int out_size) {
    const float* img     = (const float*)d_in[0];
    const float* obs_pos = (const float*)d_in[1];
    const int*   hist    = (const int*)d_in[2];
    const float* obs_rel = (const float*)d_in[3];
    const float* h0      = (const float*)d_in[4];
    const float* W_ih    = (const float*)d_in[5];
    const float* W_hh    = (const float*)d_in[6];
    const float* b_ih    = (const float*)d_in[7];
    const float* b_hh    = (const float*)d_in[8];
    const float* embed_W = (const float*)d_in[9];
    const float* embed_b = (const float*)d_in[10];
    const float* pred_W  = (const float*)d_in[11];
    const float* pred_b  = (const float*)d_in[12];
    float* out = (float*)d_out;

    cudaFuncSetAttribute(lstm_main, cudaFuncAttributeMaxDynamicSharedMemorySize, SMEM_BYTES);
    prep_all<<<1024 + 384, 256>>>(img, pred_W, W_ih, W_hh, b_ih, b_hh);
    lstm_main<<<NAGENTS / 32, 256, SMEM_BYTES>>>(obs_pos, hist, obs_rel, h0,
                                                 embed_W, embed_b, pred_W, pred_b, out);
}

// round 15
// speedup vs baseline: 1.0508x; 1.0508x over previous
#include <cuda_runtime.h>
#include <cstdint>

#define NAGENTS 8192
#define OBSLEN  20
#define PREDLEN 30
#define EMBED   64
#define HIDDEN  128
#define CNNOUT  2048
#define GATES   512   /* 4*HIDDEN */
#define KDIM    192   /* EMBED + HIDDEN */

// Weight layout (unit-paired): ulonglong2 index k*128 + h*64 + s*32 + lane:
//   s=0 -> ( (Wlo,Whi)@e0 , (Wlo,Whi)@e1 ), s=1 -> e2,e3,
//   j_lo = e*128 + h*64 + lane, j_hi = j_lo + 32.
// Per-k block = 2048 B contiguous -> chunked cp.async staging is a flat copy.
__device__ unsigned long long g_Wd[KDIM * 2 * 2 * 32 * 2];
__device__ float g_bias[GATES];
__device__ float g_imgproj[NAGENTS * 2];

// ---------------------------------------------------------------------------
__global__ void prep_all(const float* __restrict__ img,
                         const float* __restrict__ pred_W,
                         const float* __restrict__ W_ih,
                         const float* __restrict__ W_hh,
                         const float* __restrict__ b_ih,
                         const float* __restrict__ b_hh) {
    int bid = blockIdx.x;
    if (bid < 1024) {
        int warp = threadIdx.x >> 5, lane = threadIdx.x & 31;
        int n = bid * 8 + warp;
        const float4* ip = (const float4*)(img + (size_t)n * CNNOUT);
        const float4* w0 = (const float4*)(pred_W + HIDDEN);
        const float4* w1 = (const float4*)(pred_W + (HIDDEN + CNNOUT) + HIDDEN);
        float s0 = 0.f, s1 = 0.f;
        for (int i = lane; i < CNNOUT / 4; i += 32) {
            float4 v = ip[i], a = w0[i], b = w1[i];
            s0 += v.x * a.x + v.y * a.y + v.z * a.z + v.w * a.w;
            s1 += v.x * b.x + v.y * b.y + v.z * b.z + v.w * b.w;
        }
#pragma unroll
        for (int o = 16; o; o >>= 1) {
            s0 += __shfl_xor_sync(0xFFFFFFFFu, s0, o);
            s1 += __shfl_xor_sync(0xFFFFFFFFu, s1, o);
        }
        if (lane == 0) { g_imgproj[n * 2] = s0; g_imgproj[n * 2 + 1] = s1; }
    } else {
        int idx = (bid - 1024) * 256 + threadIdx.x;
        if (idx < KDIM * GATES) {
            int k = idx / GATES, j = idx % GATES;
            int e = j >> 7, r = j & 127;
            int h = r >> 6, l6 = r & 63;
            int lane = l6 & 31, hi = l6 >> 5;     // hi: 0 = j_lo, 1 = j_hi
            int s = e >> 1;
            float v = (k < EMBED) ? W_ih[j * EMBED + k] : W_hh[j * HIDDEN + (k - EMBED)];
            ((float*)g_Wd)[(((((k * 2 + h) * 2 + s) * 32 + lane)) << 2) + (e & 1) * 2 + hi] = v;
        }
        if (idx < GATES) g_bias[idx] = b_ih[idx] + b_hh[idx];
    }
}

__device__ __forceinline__ float sigf(float x) {
    return __fdividef(1.f, 1.f + __expf(-x));
}
__device__ __forceinline__ float tanhfast(float x) {
    float e = __expf(-2.f * fabsf(x));
    float r = __fdividef(1.f - e, 1.f + e);
    return copysignf(r, x);
}
__device__ __forceinline__ unsigned long long pack2(float lo, float hi) {
    unsigned long long r;
    asm("mov.b64 %0, {%1, %2};" : "=l"(r) : "f"(lo), "f"(hi));
    return r;
}
__device__ __forceinline__ float2 unpk(unsigned long long v) {
    float2 r;
    asm("mov.b64 {%0, %1}, %2;" : "=f"(r.x), "=f"(r.y) : "l"(v));
    return r;
}
__device__ __forceinline__ uint32_t smem_u32(const void* p) {
    uint32_t a;
    asm("{ .reg .u64 t; cvta.to.shared.u64 t, %1; cvt.u32.u64 %0, t; }" : "=r"(a) : "l"(p));
    return a;
}
#define FF2(a, w, i) asm("fma.rn.f32x2 %0, %1, %2, %0;" : "+l"(a) : "l"(w), "l"(i))
#define BARW(id) asm volatile("bar.sync %0, 64;" :: "r"(id) : "memory")
#define CP_ASYNC16(dst, src) \
    asm volatile("cp.async.cg.shared.global [%0], [%1], 16;" :: "r"(dst), "l"(src) : "memory")
#define CP_COMMIT() asm volatile("cp.async.commit_group;" ::: "memory")
#define CP_WAIT0()  asm volatile("cp.async.wait_group 0;" ::: "memory")

#define CHUNK_K   8
#define NCHUNK    (KDIM / CHUNK_K)           /* 24 */
#define CHUNK_B   (CHUNK_K * 2048)           /* 16384 bytes per chunk */
#define WSTAGE_B  (2 * CHUNK_B)              /* double buffer: 32 KB */
#define ROWPAD 8
#define IN_DUP_ULL (4 * KDIM * ROWPAD)
#define CS_FLOATS (4 * 4 * 32 * 8)
#define SMEM_BYTES (WSTAGE_B + IN_DUP_ULL * 8 + 256 * 8 + (CS_FLOATS + 192 + 256 + 192 + 32) * 4)

// ---------------------------------------------------------------------------
// 256 threads = 4 warp-pairs; 8 agents per pair. Warp (2g+half) owns units
// half*64+lane (m=0) and half*64+32+lane (m=1). f32x2 pairs UNITS; weights
// staged gmem->smem once per block via double-buffered cp.async (kills the
// 8x redundant per-warp L2 streaming); inputs pre-duplicated (v,v) in smem;
// c state in smem (register relief: stay under the 128-reg FFMA2 cliff).
// ---------------------------------------------------------------------------
__global__ __launch_bounds__(256, 2) void lstm_main(
    const float* __restrict__ obs_pos, const int* __restrict__ hist,
    const float* __restrict__ obs_rel, const float* __restrict__ h0,
    const float* __restrict__ embed_W, const float* __restrict__ embed_b,
    const float* __restrict__ pred_W,  const float* __restrict__ pred_b,
    float* __restrict__ out) {
    extern __shared__ unsigned long long smu[];
    unsigned long long* wstage = smu;                                  // 32 KB, 2 stages
    unsigned long long (*in_dup)[KDIM][ROWPAD] =
        (unsigned long long(*)[KDIM][ROWPAD])(smu + WSTAGE_B / 8);     // [g][k][a]=(v,v)
    unsigned long long (*b2_s)[32][4] =
        (unsigned long long(*)[32][4])(smu + WSTAGE_B / 8 + IN_DUP_ULL);
    float* fb = (float*)(smu + WSTAGE_B / 8 + IN_DUP_ULL + 256);
    float (*c_s)[4][32][8] = (float(*)[4][32][8])fb;                   // [g][hm][lane][a]
    float* ew0 = fb + CS_FLOATS;
    float* ew1 = ew0 + 64;
    float* eb  = ew1 + 64;
    float* pw  = eb + 64;         // [2][128]
    float (*src_s)[8][2]  = (float(*)[8][2])(pw + 256);
    float (*pos_s)[8][2]  = (float(*)[8][2])(pw + 256 + 64);
    float (*imgp_s)[8][2] = (float(*)[8][2])(pw + 256 + 128);
    int*   hist_s         = (int*)(pw + 256 + 192);

    int tid = threadIdx.x, warp = tid >> 5, lane = tid & 31;
    int g = warp >> 1, half = warp & 1;
    int ab = blockIdx.x * 32;
    int a0 = g * 8;
    int barid = g + 1;
    uint32_t wstage_u = smem_u32(wstage);

    // ---------------- init ----------------
    for (int i = tid; i < GATES; i += 256) {
        int h = i >> 7, lane_i = (i >> 2) & 31, e = i & 3;
        int jlo = e * 128 + h * 64 + lane_i;
        b2_s[h][lane_i][e] = pack2(g_bias[jlo], g_bias[jlo + 32]);
    }
    if (tid < EMBED) {
        ew0[tid] = embed_W[tid * 2];
        ew1[tid] = embed_W[tid * 2 + 1];
        eb[tid]  = embed_b[tid];
    }
    for (int i = tid; i < 2 * HIDDEN; i += 256)
        pw[i] = pred_W[(i >> 7) * (HIDDEN + CNNOUT) + (i & 127)];
    if (tid < 32) hist_s[tid] = hist[ab + tid];
    if (tid < 64) {
        int a = tid >> 1, d = tid & 1;
        pos_s[a >> 3][a & 7][d]  = obs_pos[(size_t)(ab + a) * OBSLEN * 2 + (OBSLEN - 1) * 2 + d];
        imgp_s[a >> 3][a & 7][d] = g_imgproj[(ab + a) * 2 + d];
    }
    for (int i = tid; i < IN_DUP_ULL; i += 256) {
        int k = (i / ROWPAD) % KDIM;
        float v = (k < EMBED) ? 0.f : h0[k - EMBED];
        ((unsigned long long*)in_dup)[i] = pack2(v, v);
    }
#pragma unroll
    for (int m = 0; m < 2; m++) {
        float hv = h0[half * 64 + lane + 32 * m];
#pragma unroll
        for (int a = 0; a < 8; a++) c_s[g][half * 2 + m][lane][a] = hv;
    }
    float pbd = pred_b[(lane >> 2) & 1];
    __syncthreads();

    const char* wsrc = (const char*)g_Wd;

    // ---------------- 49 sequential steps (all warps run all steps) --------
    for (int step = 0; step < OBSLEN - 1 + PREDLEN; step++) {
        bool obsPhase = step < OBSLEN - 1;
        int t = obsPhase ? (step + 1) : (step - (OBSLEN - 1));

        // kick off chunk 0 load; overlaps with src/disp/embed phase.
        // stage 0 was last consumed as chunk 22 of the previous step; all
        // warps passed that step's c=23 __syncthreads, so it is free.
        {
            const char* src = wsrc + 0 * (size_t)CHUNK_B;
            uint32_t dst = wstage_u;   // stage 0
#pragma unroll
            for (int r = 0; r < 4; r++)
                CP_ASYNC16(dst + r * 4096 + tid * 16, src + r * 4096 + tid * 16);
            CP_COMMIT();
        }

        if (obsPhase) {
            if (half == 0 && lane < 16) {
                int a = lane >> 1, d = lane & 1;
                src_s[g][a][d] = obs_rel[(size_t)(ab + a0 + a) * OBSLEN * 2 + t * 2 + d];
            }
            BARW(barid);
        } else {
            // disp = h @ pred_W[:, :128].T + img_proj + pred_b
            int task = lane >> 2, sub = lane & 3;
            int a = half * 4 + (task >> 1), d = task & 1;
            const float* inf = (const float*)in_dup[g];
            float s = 0.f;
#pragma unroll 8
            for (int kk = 0; kk < 32; kk++) {
                int k = sub * 32 + kk;
                s = fmaf(pw[d * 128 + k], inf[((EMBED + k) * ROWPAD + a) * 2], s);
            }
            s += __shfl_xor_sync(0xFFFFFFFFu, s, 1);
            s += __shfl_xor_sync(0xFFFFFFFFu, s, 2);
            if (sub == 0) {
                s += imgp_s[g][a][d] + pbd;
                float p = pos_s[g][a][d] + s;
                pos_s[g][a][d] = p;
                out[(size_t)(ab + a0 + a) * PREDLEN * 2 + t * 2 + d] = p;
                src_s[g][a][d] = s;
            }
            BARW(barid);
        }

        // embed -> duplicated input rows (warp h writes rows h*32..h*32+31)
        {
            int k = half * 32 + lane;
            float w0 = ew0[k], w1 = ew1[k], bb = eb[k];
#pragma unroll
            for (int a = 0; a < 8; a++) {
                float x = fmaxf(fmaf(w0, src_s[g][a][0], fmaf(w1, src_s[g][a][1], bb)), 0.f);
                in_dup[g][k][a] = pack2(x, x);
            }
        }
        BARW(barid);

        // ---- gate GEMM over 24 chunks of 8 k, weights double-buffered ----
        unsigned long long acc[4][8];
#pragma unroll
        for (int e = 0; e < 4; e++) {
            unsigned long long b = b2_s[half][lane][e];
#pragma unroll
            for (int a = 0; a < 8; a++) acc[e][a] = b;
        }
        const ulonglong2* inp = (const ulonglong2*)in_dup[g];

#pragma unroll 1
        for (int c = 0; c < NCHUNK; c++) {
            CP_WAIT0();            // chunk c resident in stage c&1
            __syncthreads();       // all warps: c ready, stage (c+1)&1 free
            if (c + 1 < NCHUNK) {  // prefetch next chunk into the other stage
                const char* src = wsrc + (size_t)(c + 1) * CHUNK_B;
                uint32_t dst = wstage_u + ((c + 1) & 1) * CHUNK_B;
#pragma unroll
                for (int r = 0; r < 4; r++)
                    CP_ASYNC16(dst + r * 4096 + tid * 16, src + r * 4096 + tid * 16);
                CP_COMMIT();
            }
            // consume: weights at stage ull2 index kc*128 + half*64 + s*32 + lane
            const ulonglong2* ws =
                (const ulonglong2*)(wstage + (size_t)(c & 1) * (CHUNK_B / 8))
                + half * 64 + lane;
#pragma unroll
            for (int kc = 0; kc < CHUNK_K; kc++) {
                int k = c * CHUNK_K + kc;
                ulonglong2 w01 = ws[kc * 128], w23 = ws[kc * 128 + 32];
                ulonglong2 iA = inp[4 * k],     iB = inp[4 * k + 1];
                ulonglong2 iC = inp[4 * k + 2], iD = inp[4 * k + 3];
                FF2(acc[0][0], w01.x, iA.x); FF2(acc[1][0], w01.y, iA.x);
                FF2(acc[2][0], w23.x, iA.x); FF2(acc[3][0], w23.y, iA.x);
                FF2(acc[0][1], w01.x, iA.y); FF2(acc[1][1], w01.y, iA.y);
                FF2(acc[2][1], w23.x, iA.y); FF2(acc[3][1], w23.y, iA.y);
                FF2(acc[0][2], w01.x, iB.x); FF2(acc[1][2], w01.y, iB.x);
                FF2(acc[2][2], w23.x, iB.x); FF2(acc[3][2], w23.y, iB.x);
                FF2(acc[0][3], w01.x, iB.y); FF2(acc[1][3], w01.y, iB.y);
                FF2(acc[2][3], w23.x, iB.y); FF2(acc[3][3], w23.y, iB.y);
                FF2(acc[0][4], w01.x, iC.x); FF2(acc[1][4], w01.y, iC.x);
                FF2(acc[2][4], w23.x, iC.x); FF2(acc[3][4], w23.y, iC.x);
                FF2(acc[0][5], w01.x, iC.y); FF2(acc[1][5], w01.y, iC.y);
                FF2(acc[2][5], w23.x, iC.y); FF2(acc[3][5], w23.y, iC.y);
                FF2(acc[0][6], w01.x, iD.x); FF2(acc[1][6], w01.y, iD.x);
                FF2(acc[2][6], w23.x, iD.x); FF2(acc[3][6], w23.y, iD.x);
                FF2(acc[0][7], w01.x, iD.y); FF2(acc[1][7], w01.y, iD.y);
                FF2(acc[2][7], w23.x, iD.y); FF2(acc[3][7], w23.y, iD.y);
            }
        }

        // ---- cell update (c in shared); h written back duplicated ----
        bool upd[8];
#pragma unroll
        for (int a = 0; a < 8; a++)
            upd[a] = !obsPhase || (hist_s[a0 + a] > OBSLEN - t);
        float* cp0 = c_s[g][half * 2 + 0][lane];
        float* cp1 = c_s[g][half * 2 + 1][lane];
        float h2[2][8];
#pragma unroll
        for (int a = 0; a < 8; a++) {
            float2 I = unpk(acc[0][a]);
            float2 F = unpk(acc[1][a]);
            float2 G = unpk(acc[2][a]);
            float2 O = unpk(acc[3][a]);
            if (upd[a]) {
                float c20 = sigf(F.x) * cp0[a] + sigf(I.x) * tanhfast(G.x);
                float c21 = sigf(F.y) * cp1[a] + sigf(I.y) * tanhfast(G.y);
                cp0[a] = c20; cp1[a] = c21;
                h2[0][a] = sigf(O.x) * tanhfast(c20);
                h2[1][a] = sigf(O.y) * tanhfast(c21);
            } else {
                h2[0][a] = unpk(in_dup[g][EMBED + half * 64 + lane][a]).x;
                h2[1][a] = unpk(in_dup[g][EMBED + half * 64 + 32 + lane][a]).x;
            }
        }
#pragma unroll
        for (int m = 0; m < 2; m++) {
            int row = EMBED + half * 64 + 32 * m + lane;
#pragma unroll
            for (int a = 0; a < 8; a++)
                in_dup[g][row][a] = pack2(h2[m][a], h2[m][a]);
        }
        BARW(barid);   // h visible to partner warp
    }
}

extern "C" void kernel_launch(void* const* d_in, const int* in_sizes, int n_in,
                              void* d_out, int out_size) {
    const float* img     = (const float*)d_in[0];
    const float* obs_pos = (const float*)d_in[1];
    const int*   hist    = (const int*)d_in[2];
    const float* obs_rel = (const float*)d_in[3];
    const float* h0      = (const float*)d_in[4];
    const float* W_ih    = (const float*)d_in[5];
    const float* W_hh    = (const float*)d_in[6];
    const float* b_ih    = (const float*)d_in[7];
    const float* b_hh    = (const float*)d_in[8];
    const float* embed_W = (const float*)d_in[9];
    const float* embed_b = (const float*)d_in[10];
    const float* pred_W  = (const float*)d_in[11];
    const float* pred_b  = (const float*)d_in[12];
    float* out = (float*)d_out;

    cudaFuncSetAttribute(lstm_main, cudaFuncAttributeMaxDynamicSharedMemorySize, SMEM_BYTES);
    prep_all<<<1024 + 384, 256>>>(img, pred_W, W_ih, W_hh, b_ih, b_hh);
    lstm_main<<<NAGENTS / 32, 256, SMEM_BYTES>>>(obs_pos, hist, obs_rel, h0,
                                                 embed_W, embed_b, pred_W, pred_b, out);
}

// round 16
// speedup vs baseline: 1.1927x; 1.1350x over previous
#include <cuda_runtime.h>
#include <cstdint>

#define NAGENTS 8192
#define OBSLEN  20
#define PREDLEN 30
#define EMBED   64
#define HIDDEN  128
#define CNNOUT  2048
#define GATES   512   /* 4*HIDDEN */
#define KDIM    192   /* EMBED + HIDDEN */

// Weight layout (R12, per-unit float4): g_Wv[(k*4+mm)*32+lane] = (i,f,g,o)
// of hidden unit mm*32+lane at input k (j = e*128 + mm*32 + lane).
// Per-k block = 128 float4 = 2048 B contiguous -> flat cp.async chunks.
__device__ float4 g_Wv[KDIM * 4 * 32];
__device__ float g_bias[GATES];
__device__ float g_imgproj[NAGENTS * 2];

// ---------------------------------------------------------------------------
__global__ void prep_all(const float* __restrict__ img,
                         const float* __restrict__ pred_W,
                         const float* __restrict__ W_ih,
                         const float* __restrict__ W_hh,
                         const float* __restrict__ b_ih,
                         const float* __restrict__ b_hh) {
    int bid = blockIdx.x;
    if (bid < 1024) {
        int warp = threadIdx.x >> 5, lane = threadIdx.x & 31;
        int n = bid * 8 + warp;
        const float4* ip = (const float4*)(img + (size_t)n * CNNOUT);
        const float4* w0 = (const float4*)(pred_W + HIDDEN);
        const float4* w1 = (const float4*)(pred_W + (HIDDEN + CNNOUT) + HIDDEN);
        float s0 = 0.f, s1 = 0.f;
        for (int i = lane; i < CNNOUT / 4; i += 32) {
            float4 v = ip[i], a = w0[i], b = w1[i];
            s0 += v.x * a.x + v.y * a.y + v.z * a.z + v.w * a.w;
            s1 += v.x * b.x + v.y * b.y + v.z * b.z + v.w * b.w;
        }
#pragma unroll
        for (int o = 16; o; o >>= 1) {
            s0 += __shfl_xor_sync(0xFFFFFFFFu, s0, o);
            s1 += __shfl_xor_sync(0xFFFFFFFFu, s1, o);
        }
        if (lane == 0) { g_imgproj[n * 2] = s0; g_imgproj[n * 2 + 1] = s1; }
    } else {
        int idx = (bid - 1024) * 256 + threadIdx.x;
        if (idx < KDIM * GATES) {
            int k = idx / GATES, j = idx % GATES;
            int e = j >> 7, mm = (j >> 5) & 3, lane = j & 31;
            float v = (k < EMBED) ? W_ih[j * EMBED + k] : W_hh[j * HIDDEN + (k - EMBED)];
            ((float*)g_Wv)[(((k * 4 + mm) * 32 + lane) << 2) + e] = v;
        }
        if (idx < GATES) g_bias[idx] = b_ih[idx] + b_hh[idx];
    }
}

__device__ __forceinline__ float sigf(float x) {
    return __fdividef(1.f, 1.f + __expf(-x));
}
__device__ __forceinline__ float tanhfast(float x) {
    float e = __expf(-2.f * fabsf(x));
    float r = __fdividef(1.f - e, 1.f + e);
    return copysignf(r, x);
}
__device__ __forceinline__ unsigned long long pack2(float lo, float hi) {
    unsigned long long r;
    asm("mov.b64 %0, {%1, %2};" : "=l"(r) : "f"(lo), "f"(hi));
    return r;
}
__device__ __forceinline__ float2 unpk(unsigned long long v) {
    float2 r;
    asm("mov.b64 {%0, %1}, %2;" : "=f"(r.x), "=f"(r.y) : "l"(v));
    return r;
}
__device__ __forceinline__ uint32_t smem_u32(const void* p) {
    uint32_t a;
    asm("{ .reg .u64 t; cvta.to.shared.u64 t, %1; cvt.u32.u64 %0, t; }" : "=r"(a) : "l"(p));
    return a;
}
#define FF2(a, w, i) asm("fma.rn.f32x2 %0, %1, %2, %0;" : "+l"(a) : "l"(w), "l"(i))
#define BARW(id) asm volatile("bar.sync %0, 64;" :: "r"(id) : "memory")
#define CP_ASYNC16(dst, src) \
    asm volatile("cp.async.cg.shared.global [%0], [%1], 16;" :: "r"(dst), "l"(src) : "memory")
#define CP_COMMIT() asm volatile("cp.async.commit_group;" ::: "memory")
#define CP_WAIT0()  asm volatile("cp.async.wait_group 0;" ::: "memory")
#define CP_WAIT1()  asm volatile("cp.async.wait_group 1;" ::: "memory")

#define CHUNK_K   8
#define NCHUNK    (KDIM / CHUNK_K)           /* 24 */
#define CHUNK_B   (CHUNK_K * 2048)           /* 16384 bytes per chunk */
#define NSTAGE    3
#define WSTAGE_B  (NSTAGE * CHUNK_B)         /* 48 KB ring */
#define WSTAGE_ULL (WSTAGE_B / 8)
#define IN_G_ULL  (4 * KDIM * 4)             /* [4][192][2] ulonglong2 = 24 KB */
#define CS_FLOATS (4 * 4 * 32 * 8)
#define SMEM_BYTES (WSTAGE_B + IN_G_ULL * 8 + 512 * 8 + (CS_FLOATS + 192 + 256 + 192 + 32) * 4)

// ---------------------------------------------------------------------------
// 256 threads = 4 warp-pairs; 8 agents per pair. Warp (2g+half) owns units
// (half*2+m)*32+lane, m in {0,1}. f32x2 accumulators pair AGENTS: inputs
// stored as natural (a,a+1) pairs in smem (no dup, 2 uniform LDS/k);
// weights per-unit float4 staged gmem->smem via 3-deep cp.async ring
// (4 wf/k/warp), duplicated in-register (16 MOV/k — ALU has slack).
// c state in smem (stay under the 128-reg cliff where FFMA2 demotes).
// ---------------------------------------------------------------------------
__global__ __launch_bounds__(256, 2) void lstm_main(
    const float* __restrict__ obs_pos, const int* __restrict__ hist,
    const float* __restrict__ obs_rel, const float* __restrict__ h0,
    const float* __restrict__ embed_W, const float* __restrict__ embed_b,
    const float* __restrict__ pred_W,  const float* __restrict__ pred_b,
    float* __restrict__ out) {
    extern __shared__ unsigned long long smu[];
    unsigned long long* wstage = smu;                                  // 48 KB, 3 stages
    ulonglong2 (*in_g)[KDIM][2] =
        (ulonglong2(*)[KDIM][2])(smu + WSTAGE_ULL);                    // [g][k][2]: 4 (a,a+1) pairs
    unsigned long long (*b2_s)[32][4] =
        (unsigned long long(*)[32][4])(smu + WSTAGE_ULL + IN_G_ULL);   // [mm][lane][e]
    float* fb = (float*)(smu + WSTAGE_ULL + IN_G_ULL + 512);
    float (*c_s)[4][32][8] = (float(*)[4][32][8])fb;                   // [g][hm][lane][a]
    float* ew0 = fb + CS_FLOATS;
    float* ew1 = ew0 + 64;
    float* eb  = ew1 + 64;
    float* pw  = eb + 64;         // [2][128]
    float (*src_s)[8][2]  = (float(*)[8][2])(pw + 256);
    float (*pos_s)[8][2]  = (float(*)[8][2])(pw + 256 + 64);
    float (*imgp_s)[8][2] = (float(*)[8][2])(pw + 256 + 128);
    int*   hist_s         = (int*)(pw + 256 + 192);

    int tid = threadIdx.x, warp = tid >> 5, lane = tid & 31;
    int g = warp >> 1, half = warp & 1;
    int ab = blockIdx.x * 32;
    int a0 = g * 8;
    int barid = g + 1;
    uint32_t wstage_u = smem_u32(wstage);

    // ---------------- init ----------------
    for (int i = tid; i < GATES; i += 256) {
        int mm = i >> 7, ln = (i >> 2) & 31, e = i & 3;
        float b = g_bias[e * 128 + mm * 32 + ln];
        b2_s[mm][ln][e] = pack2(b, b);
    }
    if (tid < EMBED) {
        ew0[tid] = embed_W[tid * 2];
        ew1[tid] = embed_W[tid * 2 + 1];
        eb[tid]  = embed_b[tid];
    }
    for (int i = tid; i < 2 * HIDDEN; i += 256)
        pw[i] = pred_W[(i >> 7) * (HIDDEN + CNNOUT) + (i & 127)];
    if (tid < 32) hist_s[tid] = hist[ab + tid];
    if (tid < 64) {
        int a = tid >> 1, d = tid & 1;
        pos_s[a >> 3][a & 7][d]  = obs_pos[(size_t)(ab + a) * OBSLEN * 2 + (OBSLEN - 1) * 2 + d];
        imgp_s[a >> 3][a & 7][d] = g_imgproj[(ab + a) * 2 + d];
    }
    for (int i = tid; i < 4 * KDIM * 2; i += 256) {   // h0/zero init of in_g
        int gg = i / (KDIM * 2), r = i % (KDIM * 2);
        int k = r >> 1, p2 = r & 1;
        float v = (k < EMBED) ? 0.f : h0[k - EMBED];
        unsigned long long pv = pack2(v, v);
        in_g[gg][k][p2] = make_ulonglong2(pv, pv);
    }
#pragma unroll
    for (int m = 0; m < 2; m++) {
        float hv = h0[(half * 2 + m) * 32 + lane];
#pragma unroll
        for (int a = 0; a < 8; a++) c_s[g][half * 2 + m][lane][a] = hv;
    }
    float pbd = pred_b[(lane >> 2) & 1];
    __syncthreads();

    const char* wsrc = (const char*)g_Wv;

    // ---------------- 49 sequential steps ----------------
    for (int step = 0; step < OBSLEN - 1 + PREDLEN; step++) {
        bool obsPhase = step < OBSLEN - 1;
        int t = obsPhase ? (step + 1) : (step - (OBSLEN - 1));

        // kick chunk 0 -> stage 0 (stage 0 = chunk 21's, consumed before the
        // c=23 __syncthreads of the previous step's GEMM by every warp).
        {
            uint32_t dst = wstage_u;
#pragma unroll
            for (int r = 0; r < 4; r++)
                CP_ASYNC16(dst + r * 4096 + tid * 16, wsrc + r * 4096 + tid * 16);
            CP_COMMIT();
        }

        if (obsPhase) {
            if (half == 0 && lane < 16) {
                int a = lane >> 1, d = lane & 1;
                src_s[g][a][d] = obs_rel[(size_t)(ab + a0 + a) * OBSLEN * 2 + t * 2 + d];
            }
            BARW(barid);
        } else {
            // disp = h @ pred_W[:, :128].T + img_proj + pred_b
            int task = lane >> 2, sub = lane & 3;
            int a = half * 4 + (task >> 1), d = task & 1;
            const float* inf = (const float*)in_g[g];
            float s = 0.f;
#pragma unroll 8
            for (int kk = 0; kk < 32; kk++) {
                int k = sub * 32 + kk;
                s = fmaf(pw[d * 128 + k], inf[(EMBED + k) * 8 + a], s);
            }
            s += __shfl_xor_sync(0xFFFFFFFFu, s, 1);
            s += __shfl_xor_sync(0xFFFFFFFFu, s, 2);
            if (sub == 0) {
                s += imgp_s[g][a][d] + pbd;
                float p = pos_s[g][a][d] + s;
                pos_s[g][a][d] = p;
                out[(size_t)(ab + a0 + a) * PREDLEN * 2 + t * 2 + d] = p;
                src_s[g][a][d] = s;
            }
            BARW(barid);
        }

        // embed -> agent-pair input rows (warp h writes rows h*32..h*32+31)
        {
            int k = half * 32 + lane;
            float w0 = ew0[k], w1 = ew1[k], bb = eb[k];
            float x[8];
#pragma unroll
            for (int a = 0; a < 8; a++)
                x[a] = fmaxf(fmaf(w0, src_s[g][a][0], fmaf(w1, src_s[g][a][1], bb)), 0.f);
            in_g[g][k][0] = make_ulonglong2(pack2(x[0], x[1]), pack2(x[2], x[3]));
            in_g[g][k][1] = make_ulonglong2(pack2(x[4], x[5]), pack2(x[6], x[7]));
        }
        BARW(barid);

        // kick chunk 1 -> stage 1 (chunk 22's stage, same safety argument)
        {
            const char* src = wsrc + (size_t)CHUNK_B;
            uint32_t dst = wstage_u + CHUNK_B;
#pragma unroll
            for (int r = 0; r < 4; r++)
                CP_ASYNC16(dst + r * 4096 + tid * 16, src + r * 4096 + tid * 16);
            CP_COMMIT();
        }

        // ---- gate GEMM over 24 chunks, 3-stage ring ----
        unsigned long long acc[2][4][4];
#pragma unroll
        for (int m = 0; m < 2; m++)
#pragma unroll
            for (int e = 0; e < 4; e++) {
                unsigned long long b = b2_s[half * 2 + m][lane][e];
                acc[m][e][0] = b; acc[m][e][1] = b; acc[m][e][2] = b; acc[m][e][3] = b;
            }
        const ulonglong2* inp = (const ulonglong2*)in_g[g];

        int st = 0;
#pragma unroll 1
        for (int c = 0; c < NCHUNK; c++) {
            if (c < NCHUNK - 1) { CP_WAIT1(); } else { CP_WAIT0(); }
            __syncthreads();       // chunk c visible to all; stage (c+2)%3 free
            if (c + 2 < NCHUNK) {
                int stp = st + 2; if (stp >= NSTAGE) stp -= NSTAGE;
                const char* src = wsrc + (size_t)(c + 2) * CHUNK_B;
                uint32_t dst = wstage_u + stp * CHUNK_B;
#pragma unroll
                for (int r = 0; r < 4; r++)
                    CP_ASYNC16(dst + r * 4096 + tid * 16, src + r * 4096 + tid * 16);
                CP_COMMIT();
            }
            const float4* ws = (const float4*)((const char*)wstage + st * CHUNK_B)
                               + (half * 2) * 32 + lane;
#pragma unroll
            for (int kc = 0; kc < CHUNK_K; kc++) {
                int k = c * CHUNK_K + kc;
                float4 wA = ws[kc * 128], wB = ws[kc * 128 + 32];
                ulonglong2 i01 = inp[2 * k], i23 = inp[2 * k + 1];
                unsigned long long w;
#define FMA4(m, e, wf) w = pack2(wf, wf); \
                FF2(acc[m][e][0], w, i01.x); FF2(acc[m][e][1], w, i01.y); \
                FF2(acc[m][e][2], w, i23.x); FF2(acc[m][e][3], w, i23.y)
                FMA4(0, 0, wA.x); FMA4(0, 1, wA.y); FMA4(0, 2, wA.z); FMA4(0, 3, wA.w);
                FMA4(1, 0, wB.x); FMA4(1, 1, wB.y); FMA4(1, 2, wB.z); FMA4(1, 3, wB.w);
#undef FMA4
            }
            st++; if (st >= NSTAGE) st = 0;
        }

        // ---- cell update (c in shared); h written back as agent pairs ----
        bool upd[8];
#pragma unroll
        for (int a = 0; a < 8; a++)
            upd[a] = !obsPhase || (hist_s[a0 + a] > OBSLEN - t);
#pragma unroll
        for (int m = 0; m < 2; m++) {
            int row = EMBED + (half * 2 + m) * 32 + lane;
            float* cp = c_s[g][half * 2 + m][lane];
            float oldh[8];
            if (obsPhase) {
                ulonglong2 o01 = in_g[g][row][0], o23 = in_g[g][row][1];
                float2 f0 = unpk(o01.x), f1 = unpk(o01.y), f2 = unpk(o23.x), f3 = unpk(o23.y);
                oldh[0] = f0.x; oldh[1] = f0.y; oldh[2] = f1.x; oldh[3] = f1.y;
                oldh[4] = f2.x; oldh[5] = f2.y; oldh[6] = f3.x; oldh[7] = f3.y;
            }
            float h2[8];
#pragma unroll
            for (int p = 0; p < 4; p++) {
                float2 I = unpk(acc[m][0][p]);
                float2 F = unpk(acc[m][1][p]);
                float2 G = unpk(acc[m][2][p]);
                float2 O = unpk(acc[m][3][p]);
#pragma unroll
                for (int q = 0; q < 2; q++) {
                    int a = 2 * p + q;
                    float iv = q ? I.y : I.x, fv = q ? F.y : F.x;
                    float gv = q ? G.y : G.x, ov = q ? O.y : O.x;
                    if (upd[a]) {
                        float c2 = sigf(fv) * cp[a] + sigf(iv) * tanhfast(gv);
                        cp[a] = c2;
                        h2[a] = sigf(ov) * tanhfast(c2);
                    } else {
                        h2[a] = oldh[a];
                    }
                }
            }
            in_g[g][row][0] = make_ulonglong2(pack2(h2[0], h2[1]), pack2(h2[2], h2[3]));
            in_g[g][row][1] = make_ulonglong2(pack2(h2[4], h2[5]), pack2(h2[6], h2[7]));
        }
        BARW(barid);   // h visible to partner warp
    }
}

extern "C" void kernel_launch(void* const* d_in, const int* in_sizes, int n_in,
                              void* d_out, int out_size) {
    const float* img     = (const float*)d_in[0];
    const float* obs_pos = (const float*)d_in[1];
    const int*   hist    = (const int*)d_in[2];
    const float* obs_rel = (const float*)d_in[3];
    const float* h0      = (const float*)d_in[4];
    const float* W_ih    = (const float*)d_in[5];
    const float* W_hh    = (const float*)d_in[6];
    const float* b_ih    = (const float*)d_in[7];
    const float* b_hh    = (const float*)d_in[8];
    const float* embed_W = (const float*)d_in[9];
    const float* embed_b = (const float*)d_in[10];
    const float* pred_W  = (const float*)d_in[11];
    const float* pred_b  = (const float*)d_in[12];
    float* out = (float*)d_out;

    cudaFuncSetAttribute(lstm_main, cudaFuncAttributeMaxDynamicSharedMemorySize, SMEM_BYTES);
    prep_all<<<1024 + 384, 256>>>(img, pred_W, W_ih, W_hh, b_ih, b_hh);
    lstm_main<<<NAGENTS / 32, 256, SMEM_BYTES>>>(obs_pos, hist, obs_rel, h0,
                                                 embed_W, embed_b, pred_W, pred_b, out);
}